// round 6
// baseline (speedup 1.0000x reference)
#include <cuda_runtime.h>
#include <math.h>

// ---------------------------------------------------------------------------
// DBS_lstm: 3-layer LSTM (T=512, H=1024, batch=1) + output projection.
//   per layer: xg = h_prev @ W_ih^T + (b_ih+b_hh)      (sgemm64, FFMA2)
//              recurrence over t                        (lstm_layer_kernel)
//   final:     out = hs2 @ W_out^T                      (sgemm64, FFMA2)
// Sync protocol: IDENTICAL to round-3 passing version (flags + ld.acquire).
// ---------------------------------------------------------------------------

#define T_FRAMES 512
#define HID      1024
#define GATES    (4 * HID)
#define IN_DIM   85
#define OUT_N    (6890 * 3)
#define NCTA     128
#define NTHR     256

typedef unsigned long long ull;

// --------------------------- scratch (device globals) ----------------------
__device__ float    g_xg[T_FRAMES * GATES];
__device__ float    g_hsA[T_FRAMES * HID];
__device__ float    g_hsB[T_FRAMES * HID];
__device__ unsigned g_flags[NCTA];            // per-producer monotone step flags

// ------------------------- asm helpers --------------------------------------
__device__ __forceinline__ unsigned ld_acq_gpu(const unsigned* p) {
    unsigned v;
    asm volatile("ld.acquire.gpu.global.u32 %0, [%1];" : "=r"(v) : "l"(p));
    return v;
}
__device__ __forceinline__ void st_rel_gpu(unsigned* p, unsigned v) {
    asm volatile("st.release.gpu.global.u32 [%0], %1;" :: "l"(p), "r"(v));
}
__device__ __forceinline__ ull pack2_bcast(float v) {
    ull r; unsigned u = __float_as_uint(v);
    asm("mov.b64 %0, {%1, %2};" : "=l"(r) : "r"(u), "r"(u));
    return r;
}
__device__ __forceinline__ ull fma2(ull a, ull b, ull c) {
    ull d;
    asm("fma.rn.f32x2 %0, %1, %2, %3;" : "=l"(d) : "l"(a), "l"(b), "l"(c));
    return d;
}
__device__ __forceinline__ float2 unpack2(ull v) {
    unsigned lo, hi;
    asm("mov.b64 {%0, %1}, %2;" : "=r"(lo), "=r"(hi) : "l"(v));
    return make_float2(__uint_as_float(lo), __uint_as_float(hi));
}
__device__ __forceinline__ float fast_tanh(float x) {
    float y; asm("tanh.approx.f32 %0, %1;" : "=f"(y) : "f"(x)); return y;
}
__device__ __forceinline__ float fast_sig(float x) {
    return fmaf(0.5f, fast_tanh(0.5f * x), 0.5f);
}

// ======================= SGEMM: C = A @ B^T (+bias) =========================
// A:[M,K] rm, B:[N,K] rm, C:[M,N] rm. 64x64 tile, 256 threads (high occupancy,
// 3-4 CTAs/SM), 4x4 micro via packed f32x2 FMA. BK=16, double-buffered smem.
#define BM  64
#define BN  64
#define BKs 16
#define LDP 68    // pitch: 68 floats = 272B, 16B-aligned rows

__global__ __launch_bounds__(256)
void sgemm64(const float* __restrict__ A, const float* __restrict__ B,
             const float* __restrict__ b0, const float* __restrict__ b1,
             float* __restrict__ C, int M, int N, int K,
             unsigned* flag_reset)
{
    __shared__ float As[2][BKs][LDP];
    __shared__ float Bs[2][BKs][LDP];

    const int tid = threadIdx.x;

    // Zero the per-CTA step flags for the recurrence kernel that follows.
    if (flag_reset && blockIdx.x == 0 && blockIdx.y == 0 && tid < NCTA)
        flag_reset[tid] = 0u;

    const int m0  = blockIdx.y * BM;
    const int n0  = blockIdx.x * BN;
    const int lr  = tid >> 2;           // 0..63 : tile row
    const int lkq = (tid & 3) << 2;     // 0,4,8,12
    const int tx  = tid & 15;           // n micro group
    const int ty  = tid >> 4;           // m micro group (0..15)
    const bool vec4 = ((K & 3) == 0);

    ull acc2[4][2];
#pragma unroll
    for (int i = 0; i < 4; ++i) { acc2[i][0] = 0ull; acc2[i][1] = 0ull; }

    float pa[4], pb[4];

#define LOAD_T(k0)                                                          \
    {                                                                       \
        const int m = m0 + lr;                                              \
        const int n = n0 + lr;                                              \
        const int k = (k0) + lkq;                                           \
        if (vec4 && (k + 3) < K) {                                          \
            if (m < M) {                                                    \
                const float4 v = *(const float4*)(A + (size_t)m * K + k);   \
                pa[0] = v.x; pa[1] = v.y; pa[2] = v.z; pa[3] = v.w;         \
            } else { pa[0] = pa[1] = pa[2] = pa[3] = 0.f; }                 \
            if (n < N) {                                                    \
                const float4 v = *(const float4*)(B + (size_t)n * K + k);   \
                pb[0] = v.x; pb[1] = v.y; pb[2] = v.z; pb[3] = v.w;         \
            } else { pb[0] = pb[1] = pb[2] = pb[3] = 0.f; }                 \
        } else {                                                            \
            _Pragma("unroll")                                               \
            for (int j = 0; j < 4; ++j) {                                   \
                pa[j] = (m < M && (k + j) < K) ? A[(size_t)m * K + k + j] : 0.f; \
                pb[j] = (n < N && (k + j) < K) ? B[(size_t)n * K + k + j] : 0.f; \
            }                                                               \
        }                                                                   \
    }
#define STS_T(buf)                                                          \
    {                                                                       \
        _Pragma("unroll")                                                   \
        for (int j = 0; j < 4; ++j) {                                       \
            As[buf][lkq + j][lr] = pa[j];                                   \
            Bs[buf][lkq + j][lr] = pb[j];                                   \
        }                                                                   \
    }
#define COMPUTE_T(buf)                                                      \
    {                                                                       \
        _Pragma("unroll")                                                   \
        for (int kk = 0; kk < BKs; ++kk) {                                  \
            const float4 aq = *(const float4*)&As[buf][kk][ty * 4];         \
            const ull*  bp = (const ull*)&Bs[buf][kk][tx * 4];              \
            const ull bv0 = bp[0], bv1 = bp[1];                             \
            const ull p0 = pack2_bcast(aq.x);                               \
            const ull p1 = pack2_bcast(aq.y);                               \
            const ull p2 = pack2_bcast(aq.z);                               \
            const ull p3 = pack2_bcast(aq.w);                               \
            acc2[0][0] = fma2(p0, bv0, acc2[0][0]);                         \
            acc2[0][1] = fma2(p0, bv1, acc2[0][1]);                         \
            acc2[1][0] = fma2(p1, bv0, acc2[1][0]);                         \
            acc2[1][1] = fma2(p1, bv1, acc2[1][1]);                         \
            acc2[2][0] = fma2(p2, bv0, acc2[2][0]);                         \
            acc2[2][1] = fma2(p2, bv1, acc2[2][1]);                         \
            acc2[3][0] = fma2(p3, bv0, acc2[3][0]);                         \
            acc2[3][1] = fma2(p3, bv1, acc2[3][1]);                         \
        }                                                                   \
    }

    int buf = 0;
    LOAD_T(0);
    STS_T(0);
    __syncthreads();

    for (int k0 = BKs; k0 < K; k0 += BKs) {
        LOAD_T(k0);                  // prefetch next tile into registers
        COMPUTE_T(buf);
        const int nb = buf ^ 1;
        STS_T(nb);
        __syncthreads();
        buf = nb;
    }
    COMPUTE_T(buf);

    // ---- epilogue ----
#pragma unroll
    for (int i = 0; i < 4; ++i) {
        const int m = m0 + ty * 4 + i;
        if (m >= M) continue;
#pragma unroll
        for (int p = 0; p < 2; ++p) {
            const int n = n0 + tx * 4 + 2 * p;
            const float2 v2 = unpack2(acc2[i][p]);
            if (n < N) {
                float v = v2.x;
                if (b0) v += __ldg(&b0[n]);
                if (b1) v += __ldg(&b1[n]);
                C[(size_t)m * N + n] = v;
            }
            if (n + 1 < N) {
                float v = v2.y;
                if (b0) v += __ldg(&b0[n + 1]);
                if (b1) v += __ldg(&b1[n + 1]);
                C[(size_t)m * N + n + 1] = v;
            }
        }
    }
#undef LOAD_T
#undef STS_T
#undef COMPUTE_T
}

// ======================= persistent LSTM recurrence =========================
// 128 CTAs (1/SM), 256 threads. CTA owns 8 hidden units => 32 rows of W_hh,
// each row split over 8 lanes (128 weights/lane in regs as 64 packed f32x2).
// Sync protocol identical to the round-3 PASSING version.

__global__ __launch_bounds__(NTHR, 1)
void lstm_layer_kernel(const float* __restrict__ Whh,   // [4096,1024]
                       const float* __restrict__ xg,    // [512,4096] (w/ biases)
                       float* __restrict__ hs_out,      // [512,1024]
                       unsigned* __restrict__ flags)    // [128], pre-zeroed
{
    __shared__ float4 hs4[HID / 4];     // h_{t-1} broadcast copy
    __shared__ float  s_act[32];        // activated gates per local row
    __shared__ float  c_s[8];
    __shared__ float  h_s[8];

    const int tid   = threadIdx.x;
    const int cta   = blockIdx.x;
    const int base  = cta * 8;
    const int lane  = tid & 31;
    const int warp  = tid >> 5;
    const int row   = warp * 4 + (lane >> 3);   // 0..31
    const int lane8 = lane & 7;
    const int g     = row >> 3;                 // gate (i,f,g,o)
    const int u     = row & 7;

    // Stage 128 weights/thread into registers as 32 x ulonglong2 (f32x2 pairs).
    const float4* wsrc = (const float4*)(Whh + (size_t)(g * HID + base + u) * HID);
    ulonglong2 wr2[32];
#pragma unroll
    for (int jj = 0; jj < 32; ++jj) {
        const float4 w = __ldg(&wsrc[lane8 + 8 * jj]);
        wr2[jj] = *(const ulonglong2*)&w;
    }

    if (tid < 8) c_s[tid] = 0.f;
    hs4[tid] = make_float4(0.f, 0.f, 0.f, 0.f);

    const int gate_off = g * HID + base + u;
    float xgv = 0.f;
    if (lane8 == 0) xgv = __ldg(xg + gate_off);
    __syncthreads();

    for (int t = 0; t < T_FRAMES; ++t) {
        // ---- dot: 128 weights x h via 64 packed-f32x2 FMAs, 2 chains ----
        ull a01 = 0ull, a23 = 0ull;
#pragma unroll
        for (int jj = 0; jj < 32; ++jj) {
            const ulonglong2 h2 = *(const ulonglong2*)&hs4[lane8 + 8 * jj];
            a01 = fma2(wr2[jj].x, h2.x, a01);
            a23 = fma2(wr2[jj].y, h2.y, a23);
        }
        const float2 f01 = unpack2(a01);
        const float2 f23 = unpack2(a23);
        float sum = (f01.x + f01.y) + (f23.x + f23.y);
        sum += __shfl_xor_sync(0xffffffffu, sum, 1);
        sum += __shfl_xor_sync(0xffffffffu, sum, 2);
        sum += __shfl_xor_sync(0xffffffffu, sum, 4);
        if (lane8 == 0) {
            const float a = sum + xgv;
            s_act[row] = (g == 2) ? fast_tanh(a) : fast_sig(a);
        }
        __syncthreads();

        // ---- cell/hidden update + publish (warp 0) ----
        if (tid < 8) {
            const float i_ = s_act[tid];
            const float f_ = s_act[8 + tid];
            const float g_ = s_act[16 + tid];
            const float o_ = s_act[24 + tid];
            const float c  = f_ * c_s[tid] + i_ * g_;
            c_s[tid] = c;
            h_s[tid] = o_ * fast_tanh(c);
        }
        __syncwarp();
        if (tid == 0) {
            float4* dst = (float4*)(hs_out + (size_t)t * HID + base);
            __stcg(dst,     *(float4*)&h_s[0]);
            __stcg(dst + 1, *(float4*)&h_s[4]);
            st_rel_gpu(&flags[cta], (unsigned)(t + 1));   // release-publish
        }

        if (t == T_FRAMES - 1) break;

        // ---- wait: warps 0-3 each watch one 32-flag span (round-3 protocol) ----
        if (warp < 4) {
            const unsigned* fp = &flags[warp * 32 + lane];
            const unsigned target = (unsigned)(t + 1);
            while (!__all_sync(0xffffffffu, ld_acq_gpu(fp) >= target)) { }
        }
        __syncthreads();

        // ---- fetch assembled h_t, prefetch next xg ----
        hs4[tid] = __ldcg(((const float4*)(hs_out + (size_t)t * HID)) + tid);
        if (lane8 == 0)
            xgv = __ldg(xg + (size_t)(t + 1) * GATES + gate_off);
        __syncthreads();
    }
}

// ================================ launch =====================================
extern "C" void kernel_launch(void* const* d_in, const int* in_sizes, int n_in,
                              void* d_out, int out_size)
{
    (void)in_sizes; (void)n_in; (void)out_size;

    const float* x       = (const float*)d_in[0];
    const float* W_ih[3] = {(const float*)d_in[1], (const float*)d_in[5], (const float*)d_in[9]};
    const float* W_hh[3] = {(const float*)d_in[2], (const float*)d_in[6], (const float*)d_in[10]};
    const float* b_ih[3] = {(const float*)d_in[3], (const float*)d_in[7], (const float*)d_in[11]};
    const float* b_hh[3] = {(const float*)d_in[4], (const float*)d_in[8], (const float*)d_in[12]};
    const float* W_out   = (const float*)d_in[13];
    float* out = (float*)d_out;

    float *xg, *hsA, *hsB;
    unsigned* flags;
    cudaGetSymbolAddress((void**)&xg,  g_xg);
    cudaGetSymbolAddress((void**)&hsA, g_hsA);
    cudaGetSymbolAddress((void**)&hsB, g_hsB);
    cudaGetSymbolAddress((void**)&flags, g_flags);

    const dim3 blk(256);
    const dim3 grid_xg(GATES / BN, T_FRAMES / BM);                  // (64, 8)
    const dim3 grid_out((OUT_N + BN - 1) / BN, T_FRAMES / BM);      // (323, 8)

    // layer 0
    sgemm64<<<grid_xg, blk>>>(x,   W_ih[0], b_ih[0], b_hh[0], xg,
                              T_FRAMES, GATES, IN_DIM, flags);
    lstm_layer_kernel<<<NCTA, blk>>>(W_hh[0], xg, hsA, flags);

    // layer 1
    sgemm64<<<grid_xg, blk>>>(hsA, W_ih[1], b_ih[1], b_hh[1], xg,
                              T_FRAMES, GATES, HID, flags);
    lstm_layer_kernel<<<NCTA, blk>>>(W_hh[1], xg, hsB, flags);

    // layer 2
    sgemm64<<<grid_xg, blk>>>(hsB, W_ih[2], b_ih[2], b_hh[2], xg,
                              T_FRAMES, GATES, HID, flags);
    lstm_layer_kernel<<<NCTA, blk>>>(W_hh[2], xg, hsA, flags);

    // output projection
    sgemm64<<<grid_out, blk>>>(hsA, W_out, nullptr, nullptr, out,
                               T_FRAMES, OUT_N, HID, nullptr);
}

// round 8
// speedup vs baseline: 1.3006x; 1.3006x over previous
#include <cuda_runtime.h>
#include <cuda_bf16.h>
#include <math.h>
#include <cstdint>

// ---------------------------------------------------------------------------
// DBS_lstm: 3-layer LSTM (T=512, H=1024, batch=1) + output projection.
//   xg0  = x @ W_ih0^T + b     : fp32 sgemm (R1 kernel, K=85)
//   lstm recurrence x3         : R1 persistent kernel (verbatim, proven)
//   xg1, xg2, out              : split-bf16 warp-MMA GEMM (mma.sync m16n8k16)
//                                C = Ah*Bh^T + Ah*Bl^T + Al*Bh^T (fp32 acc)
// ---------------------------------------------------------------------------

#define T_FRAMES 512
#define HID      1024
#define GATES    (4 * HID)
#define IN_DIM   85
#define OUT_N    (6890 * 3)
#define NCTA_LSTM 128
#define NTHR_LSTM 256

// --------------------------- scratch (device globals) ----------------------
__device__ float    g_xg[T_FRAMES * GATES];
__device__ float    g_hsA[T_FRAMES * HID];
__device__ float    g_hsB[T_FRAMES * HID];
__device__ unsigned g_bar_count = 0;
__device__ unsigned g_bar_gen   = 0;
__device__ float4   g_h4[HID / 4];

__device__ __nv_bfloat16 g_wih_h[2][GATES * HID];   // layers 1,2
__device__ __nv_bfloat16 g_wih_l[2][GATES * HID];
__device__ __nv_bfloat16 g_wout_h[OUT_N * HID];
__device__ __nv_bfloat16 g_wout_l[OUT_N * HID];
__device__ __nv_bfloat16 g_a_h[T_FRAMES * HID];
__device__ __nv_bfloat16 g_a_l[T_FRAMES * HID];

// ------------------------------ helpers -------------------------------------
__device__ __forceinline__ uint32_t smem_u32(const void* p) {
    uint32_t a;
    asm("{ .reg .u64 t; cvta.to.shared.u64 t, %1; cvt.u32.u64 %0, t; }"
        : "=r"(a) : "l"(p));
    return a;
}

#define LDSM4(r, addr)                                                        \
    asm volatile("ldmatrix.sync.aligned.m8n8.x4.shared.b16 {%0,%1,%2,%3}, [%4];" \
        : "=r"((r)[0]), "=r"((r)[1]), "=r"((r)[2]), "=r"((r)[3]) : "r"(addr))

#define MMA_BF16(c, a, b0, b1)                                                \
    asm volatile("mma.sync.aligned.m16n8k16.row.col.f32.bf16.bf16.f32 "       \
        "{%0,%1,%2,%3}, {%4,%5,%6,%7}, {%8,%9}, {%0,%1,%2,%3};"               \
        : "+f"((c)[0]), "+f"((c)[1]), "+f"((c)[2]), "+f"((c)[3])              \
        : "r"((a)[0]), "r"((a)[1]), "r"((a)[2]), "r"((a)[3]),                 \
          "r"(b0), "r"(b1))

// ===================== fp32 -> (bf16 hi, bf16 lo) convert ====================
__global__ void split_bf16_kernel(const float* __restrict__ x,
                                  __nv_bfloat16* __restrict__ hi,
                                  __nv_bfloat16* __restrict__ lo, int n)
{
    int i = blockIdx.x * blockDim.x + threadIdx.x;
    if (i < n) {
        const float v = x[i];
        const __nv_bfloat16 h = __float2bfloat16(v);
        hi[i] = h;
        lo[i] = __float2bfloat16(v - __bfloat162float(h));
    }
}

// ============ split-bf16 warp-MMA GEMM: C = A @ B^T (+bias) ================
// A:[M,K] (hi/lo bf16, M % 64 == 0), B:[N,K] (hi/lo bf16), K % 32 == 0.
// CTA tile 64x128, 8 warps as 2(m) x 4(n), warp tile 32x32, K chunk 32.
#define WBM 64
#define WBN 128
#define WKC 32
#define APITCH 80                      // bytes per smem row (32 bf16 + pad)
#define OFF_AH 0
#define OFF_AL (OFF_AH + WBM * APITCH)     // 5120
#define OFF_BH (OFF_AL + WBM * APITCH)     // 10240
#define OFF_BL (OFF_BH + WBN * APITCH)     // 20480
#define SMEM_SZ (OFF_BL + WBN * APITCH)    // 30720

__global__ __launch_bounds__(256)
void bf16mma_gemm(const __nv_bfloat16* __restrict__ Ah,
                  const __nv_bfloat16* __restrict__ Al,
                  const __nv_bfloat16* __restrict__ Bh,
                  const __nv_bfloat16* __restrict__ Bl,
                  const float* __restrict__ b0, const float* __restrict__ b1,
                  float* __restrict__ C, int M, int N, int K)
{
    __shared__ __align__(128) char smem[SMEM_SZ];
    const uint32_t sbase = smem_u32(smem);

    const int tid  = threadIdx.x;
    const int lane = tid & 31;
    const int w    = tid >> 5;          // 0..7
    const int mrow = w & 1;             // m offset 32*mrow
    const int ncol = w >> 1;            // n offset 32*ncol
    const int m0   = blockIdx.y * WBM;
    const int n0   = blockIdx.x * WBN;

    float c[2][4][4];
#pragma unroll
    for (int i = 0; i < 2; ++i)
#pragma unroll
        for (int j = 0; j < 4; ++j)
#pragma unroll
            for (int q = 0; q < 4; ++q) c[i][j][q] = 0.f;

    // prefetch registers
    uint4 pah, pal, pbh0, pbl0, pbh1, pbl1;
    const int ar = tid >> 2, aj = tid & 3;   // A row 0..63, 16B block 0..3
    const int br0 = tid >> 2, br1 = br0 + 64;
    const uint4 zz = make_uint4(0u, 0u, 0u, 0u);

#define GLOAD(kb)                                                             \
    {                                                                         \
        const size_t ao = (size_t)(m0 + ar) * K + (kb) + aj * 8;              \
        pah = *(const uint4*)(Ah + ao);                                       \
        pal = *(const uint4*)(Al + ao);                                       \
        const int nn0 = n0 + br0, nn1 = n0 + br1;                             \
        if (nn0 < N) {                                                        \
            const size_t bo = (size_t)nn0 * K + (kb) + aj * 8;                \
            pbh0 = *(const uint4*)(Bh + bo);                                  \
            pbl0 = *(const uint4*)(Bl + bo);                                  \
        } else { pbh0 = zz; pbl0 = zz; }                                      \
        if (nn1 < N) {                                                        \
            const size_t bo = (size_t)nn1 * K + (kb) + aj * 8;                \
            pbh1 = *(const uint4*)(Bh + bo);                                  \
            pbl1 = *(const uint4*)(Bl + bo);                                  \
        } else { pbh1 = zz; pbl1 = zz; }                                      \
    }
#define STS()                                                                 \
    {                                                                         \
        *(uint4*)(smem + OFF_AH + ar * APITCH + aj * 16) = pah;               \
        *(uint4*)(smem + OFF_AL + ar * APITCH + aj * 16) = pal;               \
        *(uint4*)(smem + OFF_BH + br0 * APITCH + aj * 16) = pbh0;             \
        *(uint4*)(smem + OFF_BL + br0 * APITCH + aj * 16) = pbl0;             \
        *(uint4*)(smem + OFF_BH + br1 * APITCH + aj * 16) = pbh1;             \
        *(uint4*)(smem + OFF_BL + br1 * APITCH + aj * 16) = pbl1;             \
    }
#define COMPUTE()                                                             \
    {                                                                         \
        _Pragma("unroll")                                                     \
        for (int ks = 0; ks < WKC; ks += 16) {                                \
            uint32_t ah[2][4], al[2][4], bh[2][4], bl[2][4];                  \
            _Pragma("unroll")                                                 \
            for (int mt = 0; mt < 2; ++mt) {                                  \
                const uint32_t arow = mrow * 32 + mt * 16 + (lane & 15);      \
                const uint32_t acol = (ks + (lane >> 4) * 8) * 2;             \
                LDSM4(ah[mt], sbase + OFF_AH + arow * APITCH + acol);         \
                LDSM4(al[mt], sbase + OFF_AL + arow * APITCH + acol);         \
            }                                                                 \
            _Pragma("unroll")                                                 \
            for (int p = 0; p < 2; ++p) {                                     \
                const uint32_t brow = ncol * 32 + p * 16 + (lane & 7)         \
                                      + ((lane >> 4) & 1) * 8;                \
                const uint32_t bcol = (ks + ((lane >> 3) & 1) * 8) * 2;       \
                LDSM4(bh[p], sbase + OFF_BH + brow * APITCH + bcol);          \
                LDSM4(bl[p], sbase + OFF_BL + brow * APITCH + bcol);          \
            }                                                                 \
            _Pragma("unroll")                                                 \
            for (int mt = 0; mt < 2; ++mt)                                    \
                _Pragma("unroll")                                             \
                for (int nt = 0; nt < 4; ++nt) {                              \
                    const int p  = nt >> 1;                                   \
                    const int r0 = (nt & 1) * 2, r1 = r0 + 1;                 \
                    MMA_BF16(c[mt][nt], ah[mt], bh[p][r0], bh[p][r1]);        \
                    MMA_BF16(c[mt][nt], ah[mt], bl[p][r0], bl[p][r1]);        \
                    MMA_BF16(c[mt][nt], al[mt], bh[p][r0], bh[p][r1]);        \
                }                                                             \
        }                                                                     \
    }

    GLOAD(0);
    STS();
    __syncthreads();

    for (int kb = WKC; kb < K; kb += WKC) {
        GLOAD(kb);          // prefetch next chunk into registers
        COMPUTE();          // consume current smem
        __syncthreads();
        STS();
        __syncthreads();
    }
    COMPUTE();

    // ---- epilogue: D fragment -> global, with optional bias ----
#pragma unroll
    for (int mt = 0; mt < 2; ++mt) {
        const int mbase = m0 + mrow * 32 + mt * 16 + (lane >> 2);
#pragma unroll
        for (int nt = 0; nt < 4; ++nt) {
            const int n = n0 + ncol * 32 + nt * 8 + (lane & 3) * 2;
#pragma unroll
            for (int half = 0; half < 2; ++half) {
                const int m = mbase + half * 8;
                const float v0 = c[mt][nt][half * 2 + 0];
                const float v1 = c[mt][nt][half * 2 + 1];
                if (n < N) {
                    float v = v0;
                    if (b0) v += __ldg(&b0[n]);
                    if (b1) v += __ldg(&b1[n]);
                    C[(size_t)m * N + n] = v;
                }
                if (n + 1 < N) {
                    float v = v1;
                    if (b0) v += __ldg(&b0[n + 1]);
                    if (b1) v += __ldg(&b1[n + 1]);
                    C[(size_t)m * N + n + 1] = v;
                }
            }
        }
    }
#undef GLOAD
#undef STS
#undef COMPUTE
}

// =================== fp32 SGEMM (R1 verbatim) — layer-0 xg only =============
#define BM 64
#define BN 64
#define BK 16

__global__ __launch_bounds__(256)
void sgemm_nt_kernel(const float* __restrict__ A, const float* __restrict__ B,
                     const float* __restrict__ b0, const float* __restrict__ b1,
                     float* __restrict__ C, int M, int N, int K)
{
    __shared__ float As[BK][68];
    __shared__ float Bs[BK][68];

    const int tid = threadIdx.x;
    const int tx  = tid & 15;
    const int ty  = tid >> 4;
    const int lk  = tid & 15;
    const int lr  = tid >> 4;
    const int m0 = blockIdx.y * BM;
    const int n0 = blockIdx.x * BN;

    float acc[4][4];
#pragma unroll
    for (int i = 0; i < 4; ++i)
#pragma unroll
        for (int j = 0; j < 4; ++j) acc[i][j] = 0.f;

    for (int k0 = 0; k0 < K; k0 += BK) {
        const int k = k0 + lk;
        const bool kok = (k < K);
#pragma unroll
        for (int i = 0; i < 4; ++i) {
            const int m = m0 + lr + 16 * i;
            const int n = n0 + lr + 16 * i;
            As[lk][lr + 16 * i] = (kok && m < M) ? __ldg(&A[(size_t)m * K + k]) : 0.f;
            Bs[lk][lr + 16 * i] = (kok && n < N) ? __ldg(&B[(size_t)n * K + k]) : 0.f;
        }
        __syncthreads();
#pragma unroll
        for (int kk = 0; kk < BK; ++kk) {
            const float4 a = *(const float4*)&As[kk][ty * 4];
            const float4 b = *(const float4*)&Bs[kk][tx * 4];
            acc[0][0] = fmaf(a.x, b.x, acc[0][0]);
            acc[0][1] = fmaf(a.x, b.y, acc[0][1]);
            acc[0][2] = fmaf(a.x, b.z, acc[0][2]);
            acc[0][3] = fmaf(a.x, b.w, acc[0][3]);
            acc[1][0] = fmaf(a.y, b.x, acc[1][0]);
            acc[1][1] = fmaf(a.y, b.y, acc[1][1]);
            acc[1][2] = fmaf(a.y, b.z, acc[1][2]);
            acc[1][3] = fmaf(a.y, b.w, acc[1][3]);
            acc[2][0] = fmaf(a.z, b.x, acc[2][0]);
            acc[2][1] = fmaf(a.z, b.y, acc[2][1]);
            acc[2][2] = fmaf(a.z, b.z, acc[2][2]);
            acc[2][3] = fmaf(a.z, b.w, acc[2][3]);
            acc[3][0] = fmaf(a.w, b.x, acc[3][0]);
            acc[3][1] = fmaf(a.w, b.y, acc[3][1]);
            acc[3][2] = fmaf(a.w, b.z, acc[3][2]);
            acc[3][3] = fmaf(a.w, b.w, acc[3][3]);
        }
        __syncthreads();
    }

#pragma unroll
    for (int i = 0; i < 4; ++i) {
        const int m = m0 + ty * 4 + i;
        if (m >= M) continue;
#pragma unroll
        for (int j = 0; j < 4; ++j) {
            const int n = n0 + tx * 4 + j;
            if (n >= N) continue;
            float v = acc[i][j];
            if (b0) v += __ldg(&b0[n]);
            if (b1) v += __ldg(&b1[n]);
            C[(size_t)m * N + n] = v;
        }
    }
}

// =================== persistent LSTM recurrence (R1 verbatim) ================
__device__ __forceinline__ float sigmf(float x) { return 1.f / (1.f + expf(-x)); }

__global__ __launch_bounds__(NTHR_LSTM, 1)
void lstm_layer_kernel(const float* __restrict__ Whh,
                       const float* __restrict__ xg,
                       float* __restrict__ hs_out)
{
    __shared__ float4 hs4[HID / 4];
    __shared__ float  s_s[32];
    __shared__ float  c_s[8];

    const int tid   = threadIdx.x;
    const int cta   = blockIdx.x;
    const int base  = cta * 8;
    const int lane  = tid & 31;
    const int warp  = tid >> 5;
    const int row   = warp * 4 + (lane >> 3);
    const int lane8 = lane & 7;
    const int g     = row >> 3;
    const int u     = row & 7;

    const float4* wsrc = (const float4*)(Whh + (size_t)(g * HID + base + u) * HID);
    float4 wr[32];
#pragma unroll
    for (int jj = 0; jj < 32; ++jj)
        wr[jj] = __ldg(&wsrc[lane8 + 8 * jj]);

    if (tid < 8) c_s[tid] = 0.f;
    hs4[tid] = make_float4(0.f, 0.f, 0.f, 0.f);

    unsigned gen0 = 0;
    if (tid == 0) gen0 = *(volatile unsigned*)&g_bar_gen;
    __syncthreads();

    for (int t = 0; t < T_FRAMES; ++t) {
        float sum = 0.f;
#pragma unroll
        for (int jj = 0; jj < 32; ++jj) {
            const float4 h = hs4[lane8 + 8 * jj];
            sum = fmaf(wr[jj].x, h.x, sum);
            sum = fmaf(wr[jj].y, h.y, sum);
            sum = fmaf(wr[jj].z, h.z, sum);
            sum = fmaf(wr[jj].w, h.w, sum);
        }
        sum += __shfl_xor_sync(0xffffffffu, sum, 1);
        sum += __shfl_xor_sync(0xffffffffu, sum, 2);
        sum += __shfl_xor_sync(0xffffffffu, sum, 4);
        if (lane8 == 0) s_s[row] = sum;
        __syncthreads();

        if (tid < 8) {
            const float* xr = xg + (size_t)t * GATES + base + tid;
            const float ai = s_s[tid]      + __ldg(xr);
            const float af = s_s[8 + tid]  + __ldg(xr + HID);
            const float ag = s_s[16 + tid] + __ldg(xr + 2 * HID);
            const float ao = s_s[24 + tid] + __ldg(xr + 3 * HID);
            const float i_ = sigmf(ai);
            const float f_ = sigmf(af);
            const float g_ = tanhf(ag);
            const float o_ = sigmf(ao);
            const float cc = f_ * c_s[tid] + i_ * g_;
            c_s[tid] = cc;
            const float h = o_ * tanhf(cc);
            __stcg(((float*)g_h4) + base + tid, h);
            hs_out[(size_t)t * HID + base + tid] = h;
            __threadfence();
        }
        __syncthreads();

        if (tid == 0) {
            __threadfence();
            const unsigned prev = atomicAdd(&g_bar_count, 1u);
            if (prev == gridDim.x - 1) {
                *(volatile unsigned*)&g_bar_count = 0u;
                __threadfence();
                atomicAdd(&g_bar_gen, 1u);
            } else {
                const unsigned target = gen0 + (unsigned)t + 1u;
                while ((int)(*(volatile unsigned*)&g_bar_gen - target) < 0) { }
            }
        }
        __syncthreads();

        if (t < T_FRAMES - 1) {
            hs4[tid] = __ldcg(((const float4*)g_h4) + tid);
        }
        __syncthreads();
    }
}

// ================================ launch =====================================
extern "C" void kernel_launch(void* const* d_in, const int* in_sizes, int n_in,
                              void* d_out, int out_size)
{
    (void)in_sizes; (void)n_in; (void)out_size;

    const float* x       = (const float*)d_in[0];
    const float* W_ih[3] = {(const float*)d_in[1], (const float*)d_in[5], (const float*)d_in[9]};
    const float* W_hh[3] = {(const float*)d_in[2], (const float*)d_in[6], (const float*)d_in[10]};
    const float* b_ih[3] = {(const float*)d_in[3], (const float*)d_in[7], (const float*)d_in[11]};
    const float* b_hh[3] = {(const float*)d_in[4], (const float*)d_in[8], (const float*)d_in[12]};
    const float* W_out   = (const float*)d_in[13];
    float* out = (float*)d_out;

    float *xg, *hsA, *hsB;
    __nv_bfloat16 *wih_h, *wih_l, *wout_h, *wout_l, *a_h, *a_l;
    cudaGetSymbolAddress((void**)&xg,     g_xg);
    cudaGetSymbolAddress((void**)&hsA,    g_hsA);
    cudaGetSymbolAddress((void**)&hsB,    g_hsB);
    cudaGetSymbolAddress((void**)&wih_h,  g_wih_h);
    cudaGetSymbolAddress((void**)&wih_l,  g_wih_l);
    cudaGetSymbolAddress((void**)&wout_h, g_wout_h);
    cudaGetSymbolAddress((void**)&wout_l, g_wout_l);
    cudaGetSymbolAddress((void**)&a_h,    g_a_h);
    cudaGetSymbolAddress((void**)&a_l,    g_a_l);

    const dim3 blk256(256);
    const int  WIH_ELEMS  = GATES * HID;
    const int  WOUT_ELEMS = OUT_N * HID;
    const int  ACT_ELEMS  = T_FRAMES * HID;

    // ---- weight conversions (pure functions of inputs) ----
    split_bf16_kernel<<<(WIH_ELEMS + 255) / 256, blk256>>>(W_ih[1], wih_h, wih_l, WIH_ELEMS);
    split_bf16_kernel<<<(WIH_ELEMS + 255) / 256, blk256>>>(W_ih[2], wih_h + WIH_ELEMS,
                                                           wih_l + WIH_ELEMS, WIH_ELEMS);
    split_bf16_kernel<<<(WOUT_ELEMS + 255) / 256, blk256>>>(W_out, wout_h, wout_l, WOUT_ELEMS);

    // ---- layer 0: fp32 xg GEMM (K=85) + recurrence ----
    const dim3 grid_xg0(GATES / BN, T_FRAMES / BM);            // (64, 8)
    sgemm_nt_kernel<<<grid_xg0, blk256>>>(x, W_ih[0], b_ih[0], b_hh[0], xg,
                                          T_FRAMES, GATES, IN_DIM);
    lstm_layer_kernel<<<NCTA_LSTM, blk256>>>(W_hh[0], xg, hsA);

    // ---- layer 1 ----
    split_bf16_kernel<<<(ACT_ELEMS + 255) / 256, blk256>>>(hsA, a_h, a_l, ACT_ELEMS);
    const dim3 grid_xgt(GATES / WBN, T_FRAMES / WBM);          // (32, 8)
    bf16mma_gemm<<<grid_xgt, blk256>>>(a_h, a_l, wih_h, wih_l,
                                       b_ih[1], b_hh[1], xg,
                                       T_FRAMES, GATES, HID);
    lstm_layer_kernel<<<NCTA_LSTM, blk256>>>(W_hh[1], xg, hsB);

    // ---- layer 2 ----
    split_bf16_kernel<<<(ACT_ELEMS + 255) / 256, blk256>>>(hsB, a_h, a_l, ACT_ELEMS);
    bf16mma_gemm<<<grid_xgt, blk256>>>(a_h, a_l, wih_h + WIH_ELEMS,
                                       wih_l + WIH_ELEMS,
                                       b_ih[2], b_hh[2], xg,
                                       T_FRAMES, GATES, HID);
    lstm_layer_kernel<<<NCTA_LSTM, blk256>>>(W_hh[2], xg, hsA);

    // ---- output projection ----
    split_bf16_kernel<<<(ACT_ELEMS + 255) / 256, blk256>>>(hsA, a_h, a_l, ACT_ELEMS);
    const dim3 grid_out((OUT_N + WBN - 1) / WBN, T_FRAMES / WBM);  // (162, 8)
    bf16mma_gemm<<<grid_out, blk256>>>(a_h, a_l, wout_h, wout_l,
                                       nullptr, nullptr, out,
                                       T_FRAMES, OUT_N, HID);
}

// round 9
// speedup vs baseline: 1.4516x; 1.1161x over previous
#include <cuda_runtime.h>
#include <cuda_bf16.h>
#include <math.h>
#include <cstdint>

// ---------------------------------------------------------------------------
// DBS_lstm: 3-layer LSTM (T=512, H=1024, batch=1) + output projection.
//   xg0  : fp32 sgemm (K=85)                      [R8 verbatim]
//   lstm : persistent kernel, NEW two-level monotone barrier + parallel gates
//   xg1, xg2, out : split-bf16 warp-MMA GEMM      [R8 verbatim]
// ---------------------------------------------------------------------------

#define T_FRAMES 512
#define HID      1024
#define GATES    (4 * HID)
#define IN_DIM   85
#define OUT_N    (6890 * 3)
#define NCTA_LSTM 128
#define NTHR_LSTM 256

// --------------------------- scratch (device globals) ----------------------
__device__ float    g_xg[T_FRAMES * GATES];
__device__ float    g_hsA[T_FRAMES * HID];
__device__ float    g_hsB[T_FRAMES * HID];
__device__ float4   g_h4[HID / 4];
__device__ unsigned g_cnt1[8 * 32];    // 8 group counters, one per 128B line
__device__ unsigned g_cnt2;            // super-counter: +8 per timestep

__device__ __nv_bfloat16 g_wih_h[2][GATES * HID];   // layers 1,2
__device__ __nv_bfloat16 g_wih_l[2][GATES * HID];
__device__ __nv_bfloat16 g_wout_h[OUT_N * HID];
__device__ __nv_bfloat16 g_wout_l[OUT_N * HID];
__device__ __nv_bfloat16 g_a_h[T_FRAMES * HID];
__device__ __nv_bfloat16 g_a_l[T_FRAMES * HID];

// ------------------------------ helpers -------------------------------------
__device__ __forceinline__ uint32_t smem_u32(const void* p) {
    uint32_t a;
    asm("{ .reg .u64 t; cvta.to.shared.u64 t, %1; cvt.u32.u64 %0, t; }"
        : "=r"(a) : "l"(p));
    return a;
}
__device__ __forceinline__ unsigned ld_acq_gpu(const unsigned* p) {
    unsigned v;
    asm volatile("ld.acquire.gpu.global.u32 %0, [%1];" : "=r"(v) : "l"(p));
    return v;
}
__device__ __forceinline__ unsigned atom_add_acqrel(unsigned* p, unsigned v) {
    unsigned old;
    asm volatile("atom.acq_rel.gpu.global.add.u32 %0, [%1], %2;"
                 : "=r"(old) : "l"(p), "r"(v) : "memory");
    return old;
}
__device__ __forceinline__ float fast_tanh(float x) {
    float y; asm("tanh.approx.f32 %0, %1;" : "=f"(y) : "f"(x)); return y;
}
__device__ __forceinline__ float fast_sig(float x) {
    return fmaf(0.5f, fast_tanh(0.5f * x), 0.5f);
}

#define LDSM4(r, addr)                                                        \
    asm volatile("ldmatrix.sync.aligned.m8n8.x4.shared.b16 {%0,%1,%2,%3}, [%4];" \
        : "=r"((r)[0]), "=r"((r)[1]), "=r"((r)[2]), "=r"((r)[3]) : "r"(addr))

#define MMA_BF16(c, a, b0, b1)                                                \
    asm volatile("mma.sync.aligned.m16n8k16.row.col.f32.bf16.bf16.f32 "       \
        "{%0,%1,%2,%3}, {%4,%5,%6,%7}, {%8,%9}, {%0,%1,%2,%3};"               \
        : "+f"((c)[0]), "+f"((c)[1]), "+f"((c)[2]), "+f"((c)[3])              \
        : "r"((a)[0]), "r"((a)[1]), "r"((a)[2]), "r"((a)[3]),                 \
          "r"(b0), "r"(b1))

// ===================== fp32 -> (bf16 hi, bf16 lo) convert ====================
__global__ void split_bf16_kernel(const float* __restrict__ x,
                                  __nv_bfloat16* __restrict__ hi,
                                  __nv_bfloat16* __restrict__ lo, int n)
{
    int i = blockIdx.x * blockDim.x + threadIdx.x;
    if (i < n) {
        const float v = x[i];
        const __nv_bfloat16 h = __float2bfloat16(v);
        hi[i] = h;
        lo[i] = __float2bfloat16(v - __bfloat162float(h));
    }
}

// ============ split-bf16 warp-MMA GEMM (R8 verbatim) ========================
#define WBM 64
#define WBN 128
#define WKC 32
#define APITCH 80
#define OFF_AH 0
#define OFF_AL (OFF_AH + WBM * APITCH)
#define OFF_BH (OFF_AL + WBM * APITCH)
#define OFF_BL (OFF_BH + WBN * APITCH)
#define SMEM_SZ (OFF_BL + WBN * APITCH)

__global__ __launch_bounds__(256)
void bf16mma_gemm(const __nv_bfloat16* __restrict__ Ah,
                  const __nv_bfloat16* __restrict__ Al,
                  const __nv_bfloat16* __restrict__ Bh,
                  const __nv_bfloat16* __restrict__ Bl,
                  const float* __restrict__ b0, const float* __restrict__ b1,
                  float* __restrict__ C, int M, int N, int K)
{
    __shared__ __align__(128) char smem[SMEM_SZ];
    const uint32_t sbase = smem_u32(smem);

    const int tid  = threadIdx.x;
    const int lane = tid & 31;
    const int w    = tid >> 5;
    const int mrow = w & 1;
    const int ncol = w >> 1;
    const int m0   = blockIdx.y * WBM;
    const int n0   = blockIdx.x * WBN;

    float c[2][4][4];
#pragma unroll
    for (int i = 0; i < 2; ++i)
#pragma unroll
        for (int j = 0; j < 4; ++j)
#pragma unroll
            for (int q = 0; q < 4; ++q) c[i][j][q] = 0.f;

    uint4 pah, pal, pbh0, pbl0, pbh1, pbl1;
    const int ar = tid >> 2, aj = tid & 3;
    const int br0 = tid >> 2, br1 = br0 + 64;
    const uint4 zz = make_uint4(0u, 0u, 0u, 0u);

#define GLOAD(kb)                                                             \
    {                                                                         \
        const size_t ao = (size_t)(m0 + ar) * K + (kb) + aj * 8;              \
        pah = *(const uint4*)(Ah + ao);                                       \
        pal = *(const uint4*)(Al + ao);                                       \
        const int nn0 = n0 + br0, nn1 = n0 + br1;                             \
        if (nn0 < N) {                                                        \
            const size_t bo = (size_t)nn0 * K + (kb) + aj * 8;                \
            pbh0 = *(const uint4*)(Bh + bo);                                  \
            pbl0 = *(const uint4*)(Bl + bo);                                  \
        } else { pbh0 = zz; pbl0 = zz; }                                      \
        if (nn1 < N) {                                                        \
            const size_t bo = (size_t)nn1 * K + (kb) + aj * 8;                \
            pbh1 = *(const uint4*)(Bh + bo);                                  \
            pbl1 = *(const uint4*)(Bl + bo);                                  \
        } else { pbh1 = zz; pbl1 = zz; }                                      \
    }
#define STS()                                                                 \
    {                                                                         \
        *(uint4*)(smem + OFF_AH + ar * APITCH + aj * 16) = pah;               \
        *(uint4*)(smem + OFF_AL + ar * APITCH + aj * 16) = pal;               \
        *(uint4*)(smem + OFF_BH + br0 * APITCH + aj * 16) = pbh0;             \
        *(uint4*)(smem + OFF_BL + br0 * APITCH + aj * 16) = pbl0;             \
        *(uint4*)(smem + OFF_BH + br1 * APITCH + aj * 16) = pbh1;             \
        *(uint4*)(smem + OFF_BL + br1 * APITCH + aj * 16) = pbl1;             \
    }
#define COMPUTE()                                                             \
    {                                                                         \
        _Pragma("unroll")                                                     \
        for (int ks = 0; ks < WKC; ks += 16) {                                \
            uint32_t ah[2][4], al[2][4], bh[2][4], bl[2][4];                  \
            _Pragma("unroll")                                                 \
            for (int mt = 0; mt < 2; ++mt) {                                  \
                const uint32_t arow = mrow * 32 + mt * 16 + (lane & 15);      \
                const uint32_t acol = (ks + (lane >> 4) * 8) * 2;             \
                LDSM4(ah[mt], sbase + OFF_AH + arow * APITCH + acol);         \
                LDSM4(al[mt], sbase + OFF_AL + arow * APITCH + acol);         \
            }                                                                 \
            _Pragma("unroll")                                                 \
            for (int p = 0; p < 2; ++p) {                                     \
                const uint32_t brow = ncol * 32 + p * 16 + (lane & 7)         \
                                      + ((lane >> 4) & 1) * 8;                \
                const uint32_t bcol = (ks + ((lane >> 3) & 1) * 8) * 2;       \
                LDSM4(bh[p], sbase + OFF_BH + brow * APITCH + bcol);          \
                LDSM4(bl[p], sbase + OFF_BL + brow * APITCH + bcol);          \
            }                                                                 \
            _Pragma("unroll")                                                 \
            for (int mt = 0; mt < 2; ++mt)                                    \
                _Pragma("unroll")                                             \
                for (int nt = 0; nt < 4; ++nt) {                              \
                    const int p  = nt >> 1;                                   \
                    const int r0 = (nt & 1) * 2, r1 = r0 + 1;                 \
                    MMA_BF16(c[mt][nt], ah[mt], bh[p][r0], bh[p][r1]);        \
                    MMA_BF16(c[mt][nt], ah[mt], bl[p][r0], bl[p][r1]);        \
                    MMA_BF16(c[mt][nt], al[mt], bh[p][r0], bh[p][r1]);        \
                }                                                             \
        }                                                                     \
    }

    GLOAD(0);
    STS();
    __syncthreads();

    for (int kb = WKC; kb < K; kb += WKC) {
        GLOAD(kb);
        COMPUTE();
        __syncthreads();
        STS();
        __syncthreads();
    }
    COMPUTE();

#pragma unroll
    for (int mt = 0; mt < 2; ++mt) {
        const int mbase = m0 + mrow * 32 + mt * 16 + (lane >> 2);
#pragma unroll
        for (int nt = 0; nt < 4; ++nt) {
            const int n = n0 + ncol * 32 + nt * 8 + (lane & 3) * 2;
#pragma unroll
            for (int half = 0; half < 2; ++half) {
                const int m = mbase + half * 8;
                const float v0 = c[mt][nt][half * 2 + 0];
                const float v1 = c[mt][nt][half * 2 + 1];
                if (n < N) {
                    float v = v0;
                    if (b0) v += __ldg(&b0[n]);
                    if (b1) v += __ldg(&b1[n]);
                    C[(size_t)m * N + n] = v;
                }
                if (n + 1 < N) {
                    float v = v1;
                    if (b0) v += __ldg(&b0[n + 1]);
                    if (b1) v += __ldg(&b1[n + 1]);
                    C[(size_t)m * N + n + 1] = v;
                }
            }
        }
    }
#undef GLOAD
#undef STS
#undef COMPUTE
}

// =================== fp32 SGEMM (layer-0 xg, R8 verbatim) ===================
#define BM 64
#define BN 64
#define BK 16

__global__ __launch_bounds__(256)
void sgemm_nt_kernel(const float* __restrict__ A, const float* __restrict__ B,
                     const float* __restrict__ b0, const float* __restrict__ b1,
                     float* __restrict__ C, int M, int N, int K)
{
    __shared__ float As[BK][68];
    __shared__ float Bs[BK][68];

    const int tid = threadIdx.x;
    const int tx  = tid & 15;
    const int ty  = tid >> 4;
    const int lk  = tid & 15;
    const int lr  = tid >> 4;
    const int m0 = blockIdx.y * BM;
    const int n0 = blockIdx.x * BN;

    float acc[4][4];
#pragma unroll
    for (int i = 0; i < 4; ++i)
#pragma unroll
        for (int j = 0; j < 4; ++j) acc[i][j] = 0.f;

    for (int k0 = 0; k0 < K; k0 += BK) {
        const int k = k0 + lk;
        const bool kok = (k < K);
#pragma unroll
        for (int i = 0; i < 4; ++i) {
            const int m = m0 + lr + 16 * i;
            const int n = n0 + lr + 16 * i;
            As[lk][lr + 16 * i] = (kok && m < M) ? __ldg(&A[(size_t)m * K + k]) : 0.f;
            Bs[lk][lr + 16 * i] = (kok && n < N) ? __ldg(&B[(size_t)n * K + k]) : 0.f;
        }
        __syncthreads();
#pragma unroll
        for (int kk = 0; kk < BK; ++kk) {
            const float4 a = *(const float4*)&As[kk][ty * 4];
            const float4 b = *(const float4*)&Bs[kk][tx * 4];
            acc[0][0] = fmaf(a.x, b.x, acc[0][0]);
            acc[0][1] = fmaf(a.x, b.y, acc[0][1]);
            acc[0][2] = fmaf(a.x, b.z, acc[0][2]);
            acc[0][3] = fmaf(a.x, b.w, acc[0][3]);
            acc[1][0] = fmaf(a.y, b.x, acc[1][0]);
            acc[1][1] = fmaf(a.y, b.y, acc[1][1]);
            acc[1][2] = fmaf(a.y, b.z, acc[1][2]);
            acc[1][3] = fmaf(a.y, b.w, acc[1][3]);
            acc[2][0] = fmaf(a.z, b.x, acc[2][0]);
            acc[2][1] = fmaf(a.z, b.y, acc[2][1]);
            acc[2][2] = fmaf(a.z, b.z, acc[2][2]);
            acc[2][3] = fmaf(a.z, b.w, acc[2][3]);
            acc[3][0] = fmaf(a.w, b.x, acc[3][0]);
            acc[3][1] = fmaf(a.w, b.y, acc[3][1]);
            acc[3][2] = fmaf(a.w, b.z, acc[3][2]);
            acc[3][3] = fmaf(a.w, b.w, acc[3][3]);
        }
        __syncthreads();
    }

#pragma unroll
    for (int i = 0; i < 4; ++i) {
        const int m = m0 + ty * 4 + i;
        if (m >= M) continue;
#pragma unroll
        for (int j = 0; j < 4; ++j) {
            const int n = n0 + tx * 4 + j;
            if (n >= N) continue;
            float v = acc[i][j];
            if (b0) v += __ldg(&b0[n]);
            if (b1) v += __ldg(&b1[n]);
            C[(size_t)m * N + n] = v;
        }
    }
}

// =================== persistent LSTM recurrence ==============================
// 128 CTAs (1/SM), 256 threads. CTA owns 8 hidden units => 32 rows of W_hh,
// each row split over 8 lanes (128 weights/lane in registers).
// Barrier: two-level monotone counters. Each CTA atom.acq_rel-adds its group
// counter (8 groups of 16, separate 128B lines); the 16th arriver bumps the
// super-counter. Pollers ld.acquire the super-counter vs base + 8*(t+1).
// No resets, no fences, no hot-word convoy.

__global__ __launch_bounds__(NTHR_LSTM, 1)
void lstm_layer_kernel(const float* __restrict__ Whh,
                       const float* __restrict__ xg,
                       float* __restrict__ hs_out)
{
    __shared__ float4 hs4[HID / 4];
    __shared__ float  s_act[32];
    __shared__ __align__(16) float c_s[8];
    __shared__ __align__(16) float h_s[8];
    __shared__ unsigned s_base;

    const int tid   = threadIdx.x;
    const int cta   = blockIdx.x;
    const int base  = cta * 8;
    const int lane  = tid & 31;
    const int warp  = tid >> 5;
    const int row   = warp * 4 + (lane >> 3);   // 0..31
    const int lane8 = lane & 7;
    const int g     = row >> 3;                 // gate (i,f,g,o)
    const int u     = row & 7;

    // Stage 128 weights/thread into registers.
    const float4* wsrc = (const float4*)(Whh + (size_t)(g * HID + base + u) * HID);
    float4 wr[32];
#pragma unroll
    for (int jj = 0; jj < 32; ++jj)
        wr[jj] = __ldg(&wsrc[lane8 + 8 * jj]);

    if (tid < 8) c_s[tid] = 0.f;
    hs4[tid] = make_float4(0.f, 0.f, 0.f, 0.f);

    // Snapshot super-counter base (multiple of 4096 per launch; at most +7
    // increments can precede any CTA's snapshot, so masking is exact).
    if (tid == 0) s_base = ld_acq_gpu(&g_cnt2) & ~4095u;

    const int gate_off = g * HID + base + u;
    float xgv = 0.f;
    if (lane8 == 0) xgv = __ldg(xg + gate_off);
    __syncthreads();
    const unsigned base2 = s_base;

    for (int t = 0; t < T_FRAMES; ++t) {
        // ---- dot: 128 weights x h (R1-proven structure) ----
        float sum = 0.f;
#pragma unroll
        for (int jj = 0; jj < 32; ++jj) {
            const float4 h = hs4[lane8 + 8 * jj];
            sum = fmaf(wr[jj].x, h.x, sum);
            sum = fmaf(wr[jj].y, h.y, sum);
            sum = fmaf(wr[jj].z, h.z, sum);
            sum = fmaf(wr[jj].w, h.w, sum);
        }
        sum += __shfl_xor_sync(0xffffffffu, sum, 1);
        sum += __shfl_xor_sync(0xffffffffu, sum, 2);
        sum += __shfl_xor_sync(0xffffffffu, sum, 4);
        // activations in parallel across the 32 row-leaders
        if (lane8 == 0) {
            const float a = sum + xgv;
            s_act[row] = (g == 2) ? fast_tanh(a) : fast_sig(a);
        }
        // prefetch next xg (independent of barrier; hides LDG under the wait)
        float xgn = 0.f;
        if (lane8 == 0 && t + 1 < T_FRAMES)
            xgn = __ldg(xg + (size_t)(t + 1) * GATES + gate_off);
        __syncthreads();

        // ---- cell/hidden update (warp 0) ----
        if (tid < 8) {
            const float i_ = s_act[tid];
            const float f_ = s_act[8 + tid];
            const float g_ = s_act[16 + tid];
            const float o_ = s_act[24 + tid];
            const float cc = f_ * c_s[tid] + i_ * g_;
            c_s[tid] = cc;
            const float h = o_ * fast_tanh(cc);
            h_s[tid] = h;
            hs_out[(size_t)t * HID + base + tid] = h;   // record (no ordering)
        }
        __syncwarp();
        // ---- publish + arrive (tid 0 only: single-thread release ordering) --
        if (tid == 0) {
            float4* dst = ((float4*)g_h4) + cta * 2;
            __stcg(dst,     *(float4*)&h_s[0]);
            __stcg(dst + 1, *(float4*)&h_s[4]);
            const unsigned prev =
                atom_add_acqrel(&g_cnt1[(cta >> 4) * 32], 1u);   // group arrive
            if ((prev & 15u) == 15u)
                atom_add_acqrel(&g_cnt2, 1u);                    // group done
        }

        if (t == T_FRAMES - 1) break;

        // ---- wait: tid 0 polls the super-counter ----
        if (tid == 0) {
            const unsigned tgt = base2 + 8u * (unsigned)(t + 1);
            while ((int)(ld_acq_gpu(&g_cnt2) - tgt) < 0) { }
        }
        __syncthreads();

        // ---- fetch assembled h_t ----
        hs4[tid] = __ldcg(((const float4*)g_h4) + tid);
        xgv = xgn;
        __syncthreads();
    }
}

// ================================ launch =====================================
extern "C" void kernel_launch(void* const* d_in, const int* in_sizes, int n_in,
                              void* d_out, int out_size)
{
    (void)in_sizes; (void)n_in; (void)out_size;

    const float* x       = (const float*)d_in[0];
    const float* W_ih[3] = {(const float*)d_in[1], (const float*)d_in[5], (const float*)d_in[9]};
    const float* W_hh[3] = {(const float*)d_in[2], (const float*)d_in[6], (const float*)d_in[10]};
    const float* b_ih[3] = {(const float*)d_in[3], (const float*)d_in[7], (const float*)d_in[11]};
    const float* b_hh[3] = {(const float*)d_in[4], (const float*)d_in[8], (const float*)d_in[12]};
    const float* W_out   = (const float*)d_in[13];
    float* out = (float*)d_out;

    float *xg, *hsA, *hsB;
    __nv_bfloat16 *wih_h, *wih_l, *wout_h, *wout_l, *a_h, *a_l;
    cudaGetSymbolAddress((void**)&xg,     g_xg);
    cudaGetSymbolAddress((void**)&hsA,    g_hsA);
    cudaGetSymbolAddress((void**)&hsB,    g_hsB);
    cudaGetSymbolAddress((void**)&wih_h,  g_wih_h);
    cudaGetSymbolAddress((void**)&wih_l,  g_wih_l);
    cudaGetSymbolAddress((void**)&wout_h, g_wout_h);
    cudaGetSymbolAddress((void**)&wout_l, g_wout_l);
    cudaGetSymbolAddress((void**)&a_h,    g_a_h);
    cudaGetSymbolAddress((void**)&a_l,    g_a_l);

    const dim3 blk256(256);
    const int  WIH_ELEMS  = GATES * HID;
    const int  WOUT_ELEMS = OUT_N * HID;
    const int  ACT_ELEMS  = T_FRAMES * HID;

    // ---- weight conversions (pure functions of inputs) ----
    split_bf16_kernel<<<(WIH_ELEMS + 255) / 256, blk256>>>(W_ih[1], wih_h, wih_l, WIH_ELEMS);
    split_bf16_kernel<<<(WIH_ELEMS + 255) / 256, blk256>>>(W_ih[2], wih_h + WIH_ELEMS,
                                                           wih_l + WIH_ELEMS, WIH_ELEMS);
    split_bf16_kernel<<<(WOUT_ELEMS + 255) / 256, blk256>>>(W_out, wout_h, wout_l, WOUT_ELEMS);

    // ---- layer 0: fp32 xg GEMM (K=85) + recurrence ----
    const dim3 grid_xg0(GATES / BN, T_FRAMES / BM);            // (64, 8)
    sgemm_nt_kernel<<<grid_xg0, blk256>>>(x, W_ih[0], b_ih[0], b_hh[0], xg,
                                          T_FRAMES, GATES, IN_DIM);
    lstm_layer_kernel<<<NCTA_LSTM, blk256>>>(W_hh[0], xg, hsA);

    // ---- layer 1 ----
    split_bf16_kernel<<<(ACT_ELEMS + 255) / 256, blk256>>>(hsA, a_h, a_l, ACT_ELEMS);
    const dim3 grid_xgt(GATES / WBN, T_FRAMES / WBM);          // (32, 8)
    bf16mma_gemm<<<grid_xgt, blk256>>>(a_h, a_l, wih_h, wih_l,
                                       b_ih[1], b_hh[1], xg,
                                       T_FRAMES, GATES, HID);
    lstm_layer_kernel<<<NCTA_LSTM, blk256>>>(W_hh[1], xg, hsB);

    // ---- layer 2 ----
    split_bf16_kernel<<<(ACT_ELEMS + 255) / 256, blk256>>>(hsB, a_h, a_l, ACT_ELEMS);
    bf16mma_gemm<<<grid_xgt, blk256>>>(a_h, a_l, wih_h + WIH_ELEMS,
                                       wih_l + WIH_ELEMS,
                                       b_ih[2], b_hh[2], xg,
                                       T_FRAMES, GATES, HID);
    lstm_layer_kernel<<<NCTA_LSTM, blk256>>>(W_hh[2], xg, hsA);

    // ---- output projection ----
    split_bf16_kernel<<<(ACT_ELEMS + 255) / 256, blk256>>>(hsA, a_h, a_l, ACT_ELEMS);
    const dim3 grid_out((OUT_N + WBN - 1) / WBN, T_FRAMES / WBM);  // (162, 8)
    bf16mma_gemm<<<grid_out, blk256>>>(a_h, a_l, wout_h, wout_l,
                                       nullptr, nullptr, out,
                                       T_FRAMES, OUT_N, HID);
}

// round 10
// speedup vs baseline: 1.8124x; 1.2486x over previous
#include <cuda_runtime.h>
#include <cuda_bf16.h>
#include <math.h>
#include <cstdint>

// ---------------------------------------------------------------------------
// DBS_lstm: 3-layer LSTM (T=512, H=1024, batch=1) + output projection.
//   xg0  : fp32 sgemm (K=85)                      [R9 verbatim]
//   lstm : persistent kernel — single-hop group barrier, unit-per-warp gates
//   xg1, xg2, out : split-bf16 warp-MMA GEMM      [R9 verbatim]
// ---------------------------------------------------------------------------

#define T_FRAMES 512
#define HID      1024
#define GATES    (4 * HID)
#define IN_DIM   85
#define OUT_N    (6890 * 3)
#define NCTA_LSTM 128
#define NTHR_LSTM 256

// --------------------------- scratch (device globals) ----------------------
__device__ float    g_xg[T_FRAMES * GATES];
__device__ float    g_hsA[T_FRAMES * HID];
__device__ float    g_hsB[T_FRAMES * HID];
__device__ float4   g_h4[HID / 4];
__device__ unsigned g_cnt1[8 * 32];    // 8 group counters, one per 128B line

__device__ __nv_bfloat16 g_wih_h[2][GATES * HID];   // layers 1,2
__device__ __nv_bfloat16 g_wih_l[2][GATES * HID];
__device__ __nv_bfloat16 g_wout_h[OUT_N * HID];
__device__ __nv_bfloat16 g_wout_l[OUT_N * HID];
__device__ __nv_bfloat16 g_a_h[T_FRAMES * HID];
__device__ __nv_bfloat16 g_a_l[T_FRAMES * HID];

// ------------------------------ helpers -------------------------------------
__device__ __forceinline__ uint32_t smem_u32(const void* p) {
    uint32_t a;
    asm("{ .reg .u64 t; cvta.to.shared.u64 t, %1; cvt.u32.u64 %0, t; }"
        : "=r"(a) : "l"(p));
    return a;
}
__device__ __forceinline__ unsigned ld_acq_gpu(const unsigned* p) {
    unsigned v;
    asm volatile("ld.acquire.gpu.global.u32 %0, [%1];" : "=r"(v) : "l"(p));
    return v;
}
__device__ __forceinline__ unsigned atom_add_acqrel(unsigned* p, unsigned v) {
    unsigned old;
    asm volatile("atom.acq_rel.gpu.global.add.u32 %0, [%1], %2;"
                 : "=r"(old) : "l"(p), "r"(v) : "memory");
    return old;
}
__device__ __forceinline__ float fast_tanh(float x) {
    float y; asm("tanh.approx.f32 %0, %1;" : "=f"(y) : "f"(x)); return y;
}
__device__ __forceinline__ float fast_sig(float x) {
    return fmaf(0.5f, fast_tanh(0.5f * x), 0.5f);
}

#define LDSM4(r, addr)                                                        \
    asm volatile("ldmatrix.sync.aligned.m8n8.x4.shared.b16 {%0,%1,%2,%3}, [%4];" \
        : "=r"((r)[0]), "=r"((r)[1]), "=r"((r)[2]), "=r"((r)[3]) : "r"(addr))

#define MMA_BF16(c, a, b0, b1)                                                \
    asm volatile("mma.sync.aligned.m16n8k16.row.col.f32.bf16.bf16.f32 "       \
        "{%0,%1,%2,%3}, {%4,%5,%6,%7}, {%8,%9}, {%0,%1,%2,%3};"               \
        : "+f"((c)[0]), "+f"((c)[1]), "+f"((c)[2]), "+f"((c)[3])              \
        : "r"((a)[0]), "r"((a)[1]), "r"((a)[2]), "r"((a)[3]),                 \
          "r"(b0), "r"(b1))

// ===================== fp32 -> (bf16 hi, bf16 lo) convert ====================
__global__ void split_bf16_kernel(const float* __restrict__ x,
                                  __nv_bfloat16* __restrict__ hi,
                                  __nv_bfloat16* __restrict__ lo, int n)
{
    int i = blockIdx.x * blockDim.x + threadIdx.x;
    if (i < n) {
        const float v = x[i];
        const __nv_bfloat16 h = __float2bfloat16(v);
        hi[i] = h;
        lo[i] = __float2bfloat16(v - __bfloat162float(h));
    }
}

// ============ split-bf16 warp-MMA GEMM (R9 verbatim) ========================
#define WBM 64
#define WBN 128
#define WKC 32
#define APITCH 80
#define OFF_AH 0
#define OFF_AL (OFF_AH + WBM * APITCH)
#define OFF_BH (OFF_AL + WBM * APITCH)
#define OFF_BL (OFF_BH + WBN * APITCH)
#define SMEM_SZ (OFF_BL + WBN * APITCH)

__global__ __launch_bounds__(256)
void bf16mma_gemm(const __nv_bfloat16* __restrict__ Ah,
                  const __nv_bfloat16* __restrict__ Al,
                  const __nv_bfloat16* __restrict__ Bh,
                  const __nv_bfloat16* __restrict__ Bl,
                  const float* __restrict__ b0, const float* __restrict__ b1,
                  float* __restrict__ C, int M, int N, int K)
{
    __shared__ __align__(128) char smem[SMEM_SZ];
    const uint32_t sbase = smem_u32(smem);

    const int tid  = threadIdx.x;
    const int lane = tid & 31;
    const int w    = tid >> 5;
    const int mrow = w & 1;
    const int ncol = w >> 1;
    const int m0   = blockIdx.y * WBM;
    const int n0   = blockIdx.x * WBN;

    float c[2][4][4];
#pragma unroll
    for (int i = 0; i < 2; ++i)
#pragma unroll
        for (int j = 0; j < 4; ++j)
#pragma unroll
            for (int q = 0; q < 4; ++q) c[i][j][q] = 0.f;

    uint4 pah, pal, pbh0, pbl0, pbh1, pbl1;
    const int ar = tid >> 2, aj = tid & 3;
    const int br0 = tid >> 2, br1 = br0 + 64;
    const uint4 zz = make_uint4(0u, 0u, 0u, 0u);

#define GLOAD(kb)                                                             \
    {                                                                         \
        const size_t ao = (size_t)(m0 + ar) * K + (kb) + aj * 8;              \
        pah = *(const uint4*)(Ah + ao);                                       \
        pal = *(const uint4*)(Al + ao);                                       \
        const int nn0 = n0 + br0, nn1 = n0 + br1;                             \
        if (nn0 < N) {                                                        \
            const size_t bo = (size_t)nn0 * K + (kb) + aj * 8;                \
            pbh0 = *(const uint4*)(Bh + bo);                                  \
            pbl0 = *(const uint4*)(Bl + bo);                                  \
        } else { pbh0 = zz; pbl0 = zz; }                                      \
        if (nn1 < N) {                                                        \
            const size_t bo = (size_t)nn1 * K + (kb) + aj * 8;                \
            pbh1 = *(const uint4*)(Bh + bo);                                  \
            pbl1 = *(const uint4*)(Bl + bo);                                  \
        } else { pbh1 = zz; pbl1 = zz; }                                      \
    }
#define STS()                                                                 \
    {                                                                         \
        *(uint4*)(smem + OFF_AH + ar * APITCH + aj * 16) = pah;               \
        *(uint4*)(smem + OFF_AL + ar * APITCH + aj * 16) = pal;               \
        *(uint4*)(smem + OFF_BH + br0 * APITCH + aj * 16) = pbh0;             \
        *(uint4*)(smem + OFF_BL + br0 * APITCH + aj * 16) = pbl0;             \
        *(uint4*)(smem + OFF_BH + br1 * APITCH + aj * 16) = pbh1;             \
        *(uint4*)(smem + OFF_BL + br1 * APITCH + aj * 16) = pbl1;             \
    }
#define COMPUTE()                                                             \
    {                                                                         \
        _Pragma("unroll")                                                     \
        for (int ks = 0; ks < WKC; ks += 16) {                                \
            uint32_t ah[2][4], al[2][4], bh[2][4], bl[2][4];                  \
            _Pragma("unroll")                                                 \
            for (int mt = 0; mt < 2; ++mt) {                                  \
                const uint32_t arow = mrow * 32 + mt * 16 + (lane & 15);      \
                const uint32_t acol = (ks + (lane >> 4) * 8) * 2;             \
                LDSM4(ah[mt], sbase + OFF_AH + arow * APITCH + acol);         \
                LDSM4(al[mt], sbase + OFF_AL + arow * APITCH + acol);         \
            }                                                                 \
            _Pragma("unroll")                                                 \
            for (int p = 0; p < 2; ++p) {                                     \
                const uint32_t brow = ncol * 32 + p * 16 + (lane & 7)         \
                                      + ((lane >> 4) & 1) * 8;                \
                const uint32_t bcol = (ks + ((lane >> 3) & 1) * 8) * 2;       \
                LDSM4(bh[p], sbase + OFF_BH + brow * APITCH + bcol);          \
                LDSM4(bl[p], sbase + OFF_BL + brow * APITCH + bcol);          \
            }                                                                 \
            _Pragma("unroll")                                                 \
            for (int mt = 0; mt < 2; ++mt)                                    \
                _Pragma("unroll")                                             \
                for (int nt = 0; nt < 4; ++nt) {                              \
                    const int p  = nt >> 1;                                   \
                    const int r0 = (nt & 1) * 2, r1 = r0 + 1;                 \
                    MMA_BF16(c[mt][nt], ah[mt], bh[p][r0], bh[p][r1]);        \
                    MMA_BF16(c[mt][nt], ah[mt], bl[p][r0], bl[p][r1]);        \
                    MMA_BF16(c[mt][nt], al[mt], bh[p][r0], bh[p][r1]);        \
                }                                                             \
        }                                                                     \
    }

    GLOAD(0);
    STS();
    __syncthreads();

    for (int kb = WKC; kb < K; kb += WKC) {
        GLOAD(kb);
        COMPUTE();
        __syncthreads();
        STS();
        __syncthreads();
    }
    COMPUTE();

#pragma unroll
    for (int mt = 0; mt < 2; ++mt) {
        const int mbase = m0 + mrow * 32 + mt * 16 + (lane >> 2);
#pragma unroll
        for (int nt = 0; nt < 4; ++nt) {
            const int n = n0 + ncol * 32 + nt * 8 + (lane & 3) * 2;
#pragma unroll
            for (int half = 0; half < 2; ++half) {
                const int m = mbase + half * 8;
                const float v0 = c[mt][nt][half * 2 + 0];
                const float v1 = c[mt][nt][half * 2 + 1];
                if (n < N) {
                    float v = v0;
                    if (b0) v += __ldg(&b0[n]);
                    if (b1) v += __ldg(&b1[n]);
                    C[(size_t)m * N + n] = v;
                }
                if (n + 1 < N) {
                    float v = v1;
                    if (b0) v += __ldg(&b0[n + 1]);
                    if (b1) v += __ldg(&b1[n + 1]);
                    C[(size_t)m * N + n + 1] = v;
                }
            }
        }
    }
#undef GLOAD
#undef STS
#undef COMPUTE
}

// =================== fp32 SGEMM (layer-0 xg, R9 verbatim) ===================
#define BM 64
#define BN 64
#define BK 16

__global__ __launch_bounds__(256)
void sgemm_nt_kernel(const float* __restrict__ A, const float* __restrict__ B,
                     const float* __restrict__ b0, const float* __restrict__ b1,
                     float* __restrict__ C, int M, int N, int K)
{
    __shared__ float As[BK][68];
    __shared__ float Bs[BK][68];

    const int tid = threadIdx.x;
    const int tx  = tid & 15;
    const int ty  = tid >> 4;
    const int lk  = tid & 15;
    const int lr  = tid >> 4;
    const int m0 = blockIdx.y * BM;
    const int n0 = blockIdx.x * BN;

    float acc[4][4];
#pragma unroll
    for (int i = 0; i < 4; ++i)
#pragma unroll
        for (int j = 0; j < 4; ++j) acc[i][j] = 0.f;

    for (int k0 = 0; k0 < K; k0 += BK) {
        const int k = k0 + lk;
        const bool kok = (k < K);
#pragma unroll
        for (int i = 0; i < 4; ++i) {
            const int m = m0 + lr + 16 * i;
            const int n = n0 + lr + 16 * i;
            As[lk][lr + 16 * i] = (kok && m < M) ? __ldg(&A[(size_t)m * K + k]) : 0.f;
            Bs[lk][lr + 16 * i] = (kok && n < N) ? __ldg(&B[(size_t)n * K + k]) : 0.f;
        }
        __syncthreads();
#pragma unroll
        for (int kk = 0; kk < BK; ++kk) {
            const float4 a = *(const float4*)&As[kk][ty * 4];
            const float4 b = *(const float4*)&Bs[kk][tx * 4];
            acc[0][0] = fmaf(a.x, b.x, acc[0][0]);
            acc[0][1] = fmaf(a.x, b.y, acc[0][1]);
            acc[0][2] = fmaf(a.x, b.z, acc[0][2]);
            acc[0][3] = fmaf(a.x, b.w, acc[0][3]);
            acc[1][0] = fmaf(a.y, b.x, acc[1][0]);
            acc[1][1] = fmaf(a.y, b.y, acc[1][1]);
            acc[1][2] = fmaf(a.y, b.z, acc[1][2]);
            acc[1][3] = fmaf(a.y, b.w, acc[1][3]);
            acc[2][0] = fmaf(a.z, b.x, acc[2][0]);
            acc[2][1] = fmaf(a.z, b.y, acc[2][1]);
            acc[2][2] = fmaf(a.z, b.z, acc[2][2]);
            acc[2][3] = fmaf(a.z, b.w, acc[2][3]);
            acc[3][0] = fmaf(a.w, b.x, acc[3][0]);
            acc[3][1] = fmaf(a.w, b.y, acc[3][1]);
            acc[3][2] = fmaf(a.w, b.z, acc[3][2]);
            acc[3][3] = fmaf(a.w, b.w, acc[3][3]);
        }
        __syncthreads();
    }

#pragma unroll
    for (int i = 0; i < 4; ++i) {
        const int m = m0 + ty * 4 + i;
        if (m >= M) continue;
#pragma unroll
        for (int j = 0; j < 4; ++j) {
            const int n = n0 + tx * 4 + j;
            if (n >= N) continue;
            float v = acc[i][j];
            if (b0) v += __ldg(&b0[n]);
            if (b1) v += __ldg(&b1[n]);
            C[(size_t)m * N + n] = v;
        }
    }
}

// =================== persistent LSTM recurrence ==============================
// 128 CTAs (1/SM), 256 threads. Warp w owns hidden unit (cta*8 + w): its 4
// gate rows of W_hh, each row split over 8 lanes (gate = lane>>3, 128
// weights/lane in registers). After the 8-lane butterfly reduce the 4 gate
// leaders (lanes 0,8,16,24) sit in the SAME warp -> activations + shfl gather
// + c/h update all in-warp, in registers. Publish: lane0 st.cg h; bar;
// tid0 fence.acq_rel.gpu + group atom (8 groups of 16 CTAs, monotone, no
// super-counter). Wait: warp0 lanes 0-7 poll the 8 group counters directly.

__global__ __launch_bounds__(NTHR_LSTM, 1)
void lstm_layer_kernel(const float* __restrict__ Whh,
                       const float* __restrict__ xg,
                       float* __restrict__ hs_out)
{
    __shared__ float4 hs4[HID / 4];

    const int tid   = threadIdx.x;
    const int cta   = blockIdx.x;
    const int base  = cta * 8;
    const int lane  = tid & 31;
    const int warp  = tid >> 5;        // unit within CTA
    const int gate  = lane >> 3;       // 0..3 = i,f,g,o
    const int lane8 = lane & 7;

    // Stage 128 weights/thread into registers (row = gate*HID + base + warp).
    const float4* wsrc =
        (const float4*)(Whh + (size_t)(gate * HID + base + warp) * HID);
    float4 wr[32];
#pragma unroll
    for (int jj = 0; jj < 32; ++jj)
        wr[jj] = __ldg(&wsrc[lane8 + 8 * jj]);

    hs4[tid] = make_float4(0.f, 0.f, 0.f, 0.f);

    // Per-lane group-counter base (warp 0, lanes 0-7). Counters are monotone,
    // +8192 per launch; <= +16 drift before snapshot, so masking is exact.
    unsigned baseg = 0;
    if (warp == 0 && lane < 8)
        baseg = ld_acq_gpu(&g_cnt1[lane * 32]) & ~8191u;

    const int gate_off = gate * HID + base + warp;
    float xgv = 0.f;
    if (lane8 == 0) xgv = __ldg(xg + gate_off);
    float c_reg = 0.f;
    __syncthreads();

    for (int t = 0; t < T_FRAMES; ++t) {
        // ---- dot: 128 weights x h ----
        float sum = 0.f;
#pragma unroll
        for (int jj = 0; jj < 32; ++jj) {
            const float4 h = hs4[lane8 + 8 * jj];
            sum = fmaf(wr[jj].x, h.x, sum);
            sum = fmaf(wr[jj].y, h.y, sum);
            sum = fmaf(wr[jj].z, h.z, sum);
            sum = fmaf(wr[jj].w, h.w, sum);
        }
        sum += __shfl_xor_sync(0xffffffffu, sum, 1);
        sum += __shfl_xor_sync(0xffffffffu, sum, 2);
        sum += __shfl_xor_sync(0xffffffffu, sum, 4);

        // activations on the 4 gate leaders (lanes 0,8,16,24)
        float act = 0.f;
        if (lane8 == 0) {
            const float a = sum + xgv;
            act = (gate == 2) ? fast_tanh(a) : fast_sig(a);
        }
        // prefetch next xg (independent; hides LDG under the barrier wait)
        float xgn = 0.f;
        if (lane8 == 0 && t + 1 < T_FRAMES)
            xgn = __ldg(xg + (size_t)(t + 1) * GATES + gate_off);

        // ---- in-warp gate gather + cell/hidden update ----
        const float i_ = __shfl_sync(0xffffffffu, act, 0);
        const float f_ = __shfl_sync(0xffffffffu, act, 8);
        const float g_ = __shfl_sync(0xffffffffu, act, 16);
        const float o_ = __shfl_sync(0xffffffffu, act, 24);
        c_reg = f_ * c_reg + i_ * g_;               // identical in all lanes
        const float h = o_ * fast_tanh(c_reg);
        if (lane == 0) {
            __stcg(((float*)g_h4) + base + warp, h);
            hs_out[(size_t)t * HID + base + warp] = h;
        }
        __syncthreads();

        // ---- arrive: tid0 publishes CTA completion (bar-transitive release) --
        if (tid == 0) {
            asm volatile("fence.acq_rel.gpu;" ::: "memory");
            atom_add_acqrel(&g_cnt1[(cta >> 4) * 32], 1u);
        }

        if (t == T_FRAMES - 1) break;

        // ---- wait: warp0 lanes 0-7 poll the 8 group counters ----
        if (warp == 0) {
            const unsigned tgt = baseg + 16u * (unsigned)(t + 1);
            bool ok;
            do {
                unsigned v = tgt;
                if (lane < 8) v = ld_acq_gpu(&g_cnt1[lane * 32]);
                ok = ((int)(v - tgt) >= 0);
            } while (!__all_sync(0xffffffffu, ok));
        }
        __syncthreads();

        // ---- fetch assembled h_t ----
        hs4[tid] = __ldcg(((const float4*)g_h4) + tid);
        xgv = xgn;
        __syncthreads();
    }
}

// ================================ launch =====================================
extern "C" void kernel_launch(void* const* d_in, const int* in_sizes, int n_in,
                              void* d_out, int out_size)
{
    (void)in_sizes; (void)n_in; (void)out_size;

    const float* x       = (const float*)d_in[0];
    const float* W_ih[3] = {(const float*)d_in[1], (const float*)d_in[5], (const float*)d_in[9]};
    const float* W_hh[3] = {(const float*)d_in[2], (const float*)d_in[6], (const float*)d_in[10]};
    const float* b_ih[3] = {(const float*)d_in[3], (const float*)d_in[7], (const float*)d_in[11]};
    const float* b_hh[3] = {(const float*)d_in[4], (const float*)d_in[8], (const float*)d_in[12]};
    const float* W_out   = (const float*)d_in[13];
    float* out = (float*)d_out;

    float *xg, *hsA, *hsB;
    __nv_bfloat16 *wih_h, *wih_l, *wout_h, *wout_l, *a_h, *a_l;
    cudaGetSymbolAddress((void**)&xg,     g_xg);
    cudaGetSymbolAddress((void**)&hsA,    g_hsA);
    cudaGetSymbolAddress((void**)&hsB,    g_hsB);
    cudaGetSymbolAddress((void**)&wih_h,  g_wih_h);
    cudaGetSymbolAddress((void**)&wih_l,  g_wih_l);
    cudaGetSymbolAddress((void**)&wout_h, g_wout_h);
    cudaGetSymbolAddress((void**)&wout_l, g_wout_l);
    cudaGetSymbolAddress((void**)&a_h,    g_a_h);
    cudaGetSymbolAddress((void**)&a_l,    g_a_l);

    const dim3 blk256(256);
    const int  WIH_ELEMS  = GATES * HID;
    const int  WOUT_ELEMS = OUT_N * HID;
    const int  ACT_ELEMS  = T_FRAMES * HID;

    // ---- weight conversions (pure functions of inputs) ----
    split_bf16_kernel<<<(WIH_ELEMS + 255) / 256, blk256>>>(W_ih[1], wih_h, wih_l, WIH_ELEMS);
    split_bf16_kernel<<<(WIH_ELEMS + 255) / 256, blk256>>>(W_ih[2], wih_h + WIH_ELEMS,
                                                           wih_l + WIH_ELEMS, WIH_ELEMS);
    split_bf16_kernel<<<(WOUT_ELEMS + 255) / 256, blk256>>>(W_out, wout_h, wout_l, WOUT_ELEMS);

    // ---- layer 0: fp32 xg GEMM (K=85) + recurrence ----
    const dim3 grid_xg0(GATES / BN, T_FRAMES / BM);            // (64, 8)
    sgemm_nt_kernel<<<grid_xg0, blk256>>>(x, W_ih[0], b_ih[0], b_hh[0], xg,
                                          T_FRAMES, GATES, IN_DIM);
    lstm_layer_kernel<<<NCTA_LSTM, blk256>>>(W_hh[0], xg, hsA);

    // ---- layer 1 ----
    split_bf16_kernel<<<(ACT_ELEMS + 255) / 256, blk256>>>(hsA, a_h, a_l, ACT_ELEMS);
    const dim3 grid_xgt(GATES / WBN, T_FRAMES / WBM);          // (32, 8)
    bf16mma_gemm<<<grid_xgt, blk256>>>(a_h, a_l, wih_h, wih_l,
                                       b_ih[1], b_hh[1], xg,
                                       T_FRAMES, GATES, HID);
    lstm_layer_kernel<<<NCTA_LSTM, blk256>>>(W_hh[1], xg, hsB);

    // ---- layer 2 ----
    split_bf16_kernel<<<(ACT_ELEMS + 255) / 256, blk256>>>(hsB, a_h, a_l, ACT_ELEMS);
    bf16mma_gemm<<<grid_xgt, blk256>>>(a_h, a_l, wih_h + WIH_ELEMS,
                                       wih_l + WIH_ELEMS,
                                       b_ih[2], b_hh[2], xg,
                                       T_FRAMES, GATES, HID);
    lstm_layer_kernel<<<NCTA_LSTM, blk256>>>(W_hh[2], xg, hsA);

    // ---- output projection ----
    split_bf16_kernel<<<(ACT_ELEMS + 255) / 256, blk256>>>(hsA, a_h, a_l, ACT_ELEMS);
    const dim3 grid_out((OUT_N + WBN - 1) / WBN, T_FRAMES / WBM);  // (162, 8)
    bf16mma_gemm<<<grid_out, blk256>>>(a_h, a_l, wout_h, wout_l,
                                       nullptr, nullptr, out,
                                       T_FRAMES, OUT_N, HID);
}